// round 11
// baseline (speedup 1.0000x reference)
#include <cuda_runtime.h>
#include <cuda_bf16.h>
#include <cstdint>
#include <math.h>

// ----------------------------------------------------------------------------
// Problem constants
// ----------------------------------------------------------------------------
#define BQ    64
#define HH_   56
#define WW_   56
#define CC    192
#define HEADS 6
#define WS    7
#define NWIN_TOT 4096          // B * 64 windows
#define NTOK  49               // WS*WS
#define HDIM  32
#define HID   768
#define MTOK  200704           // B*H*W = NWIN_TOT*NTOK
#define SCALE_Q 0.17677669529663687f

// ----------------------------------------------------------------------------
// Scratch (device globals — allocation-free per harness rules)
// ----------------------------------------------------------------------------
__device__ __nv_bfloat16 g_xw  [(size_t)MTOK * 192];   // LN output (windowed or linear)
__device__ __nv_bfloat16 g_qkv [(size_t)MTOK * 576];
__device__ __nv_bfloat16 g_attn[(size_t)MTOK * 192];
__device__ __nv_bfloat16 g_h1  [(size_t)MTOK * 768];
__device__ __nv_bfloat16 g_wqkv[2 * 576 * 192];        // transposed [N,K] bf16
__device__ __nv_bfloat16 g_wproj[2 * 192 * 192];
__device__ __nv_bfloat16 g_wfc1[2 * 768 * 192];
__device__ __nv_bfloat16 g_wfc2[2 * 192 * 768];

// ----------------------------------------------------------------------------
// Helpers
// ----------------------------------------------------------------------------
__device__ __forceinline__ void cp_async16(void* smem_ptr, const void* gmem_ptr) {
    uint32_t s = (uint32_t)__cvta_generic_to_shared(smem_ptr);
    asm volatile("cp.async.cg.shared.global [%0], [%1], 16;\n" :: "r"(s), "l"(gmem_ptr));
}
#define CP_COMMIT() asm volatile("cp.async.commit_group;\n")
#define CP_WAIT0()  asm volatile("cp.async.wait_group 0;\n")

__device__ __forceinline__ int region_of(int h) {
    return (h < HH_ - WS) ? 0 : ((h < HH_ - 3) ? 1 : 2);  // shift = 3
}

// ----------------------------------------------------------------------------
// Copy x -> d_out (residual stream lives in d_out, f32)
// ----------------------------------------------------------------------------
__global__ void copy_kernel(const float4* __restrict__ src, float4* __restrict__ dst, int n) {
    int i = blockIdx.x * blockDim.x + threadIdx.x;
    if (i < n) dst[i] = src[i];
}

// ----------------------------------------------------------------------------
// Weight transpose + cast: w[K,N] f32 -> wt[N,K] bf16
// ----------------------------------------------------------------------------
__global__ void transpose_kernel(const float* __restrict__ w, __nv_bfloat16* __restrict__ wt,
                                 int K, int N) {
    int i = blockIdx.x * blockDim.x + threadIdx.x;
    if (i < K * N) {
        int k = i / N, n = i - k * N;
        wt[n * K + k] = __float2bfloat16(w[i]);
    }
}

// ----------------------------------------------------------------------------
// LayerNorm (+optional shift + window partition) -> bf16
// windowed=1: out token t = window token (with roll by -shift); windowed=0: identity order
// one warp per token, 8 tokens per 256-thread block
// ----------------------------------------------------------------------------
__global__ void __launch_bounds__(256) ln_kernel(
    const float* __restrict__ x,
    const float* __restrict__ gamma,
    const float* __restrict__ beta,
    __nv_bfloat16* __restrict__ out,
    int shift, int windowed)
{
    int warp = threadIdx.x >> 5, lane = threadIdx.x & 31;
    int t = blockIdx.x * 8 + warp;   // < MTOK
    long src;
    if (windowed) {
        int wi = t / NTOK, n = t - wi * NTOK;
        int bimg = wi >> 6, win = wi & 63;
        int hh = (win >> 3) * WS + n / WS;
        int ww = (win & 7) * WS + n % WS;
        int h = hh + shift; if (h >= HH_) h -= HH_;
        int w = ww + shift; if (w >= WW_) w -= WW_;
        src = (long)bimg * (HH_ * WW_) + h * WW_ + w;
    } else {
        src = t;
    }
    const float* xp = x + src * CC;
    float v[6], s = 0.f, s2 = 0.f;
#pragma unroll
    for (int j = 0; j < 6; j++) {
        v[j] = xp[lane + 32 * j];
        s += v[j]; s2 += v[j] * v[j];
    }
#pragma unroll
    for (int o = 16; o > 0; o >>= 1) {
        s  += __shfl_xor_sync(0xffffffffu, s,  o);
        s2 += __shfl_xor_sync(0xffffffffu, s2, o);
    }
    float mu  = s * (1.f / CC);
    float var = s2 * (1.f / CC) - mu * mu;
    float rstd = rsqrtf(var + 1e-5f);
    __nv_bfloat16* op = out + (long)t * CC;
#pragma unroll
    for (int j = 0; j < 6; j++) {
        int c = lane + 32 * j;
        op[c] = __float2bfloat16((v[j] - mu) * rstd * gamma[c] + beta[c]);
    }
}

// ----------------------------------------------------------------------------
// GEMM: C[M, N] = A[M, K] (bf16) @ Bt[N, K]^T (bf16), fp32 accum, fused epilogues
// Tiles: BM=128, BN=64, BK=32; 256 threads, 8 warps (4x2), warp tile 32x32,
// mma.sync.m16n8k16. M is 200704 (grid.y), K in {192,768}, N in {576,192,768,192}.
// MODE 0: qkv  (bias, q-cols *= SCALE, -> bf16 [M,576])
// MODE 1: proj (bias, window-reverse + roll + residual add into f32 x)
// MODE 2: fc1  (bias + exact GELU -> bf16 [M,768])
// MODE 3: fc2  (bias + residual add into f32 x [M,192])
// ----------------------------------------------------------------------------
template<int MODE>
__global__ void __launch_bounds__(256, 1) gemm_k(
    const __nv_bfloat16* __restrict__ A,
    const __nv_bfloat16* __restrict__ Bt,
    const float* __restrict__ bias,
    __nv_bfloat16* __restrict__ outb,
    float* __restrict__ outf,
    int K, int shift)
{
    __shared__ __nv_bfloat16 As[2][128 * 40];
    __shared__ __nv_bfloat16 Bs[2][64 * 40];

    const int tid  = threadIdx.x;
    const int lane = tid & 31, warp = tid >> 5;
    const int wm = warp >> 1, wn = warp & 1;
    const long mbase = (long)blockIdx.y * 128;
    const int  nbase = blockIdx.x * 64;

    const __nv_bfloat16* Ag = A  + mbase * K;
    const __nv_bfloat16* Bg = Bt + (long)nbase * K;

    const int lrow = tid >> 2;        // 0..63
    const int lcol = (tid & 3) * 8;   // 0,8,16,24

    float acc[2][4][4];
#pragma unroll
    for (int i = 0; i < 2; i++)
#pragma unroll
        for (int j = 0; j < 4; j++)
#pragma unroll
            for (int e = 0; e < 4; e++) acc[i][j][e] = 0.f;

    const int KT = K / 32;

    auto loadst = [&](int buf, int kt) {
        int kb = kt * 32;
        cp_async16(&As[buf][ lrow       * 40 + lcol], Ag + (long)lrow        * K + kb + lcol);
        cp_async16(&As[buf][(lrow + 64) * 40 + lcol], Ag + (long)(lrow + 64) * K + kb + lcol);
        cp_async16(&Bs[buf][ lrow       * 40 + lcol], Bg + (long)lrow        * K + kb + lcol);
        CP_COMMIT();
    };

    loadst(0, 0);
    CP_WAIT0();
    __syncthreads();

    int buf = 0;
    for (int kt = 0; kt < KT; kt++) {
        if (kt + 1 < KT) loadst(buf ^ 1, kt + 1);

#pragma unroll
        for (int kk = 0; kk < 2; kk++) {
            const int c0 = kk * 16 + (lane & 3) * 2;
            uint32_t a[2][4], b[4][2];
            const int r0 = wm * 32 + (lane >> 2);
#pragma unroll
            for (int mi = 0; mi < 2; mi++) {
                int rr = r0 + mi * 16;
                a[mi][0] = *(const uint32_t*)&As[buf][ rr      * 40 + c0];
                a[mi][1] = *(const uint32_t*)&As[buf][(rr + 8) * 40 + c0];
                a[mi][2] = *(const uint32_t*)&As[buf][ rr      * 40 + c0 + 8];
                a[mi][3] = *(const uint32_t*)&As[buf][(rr + 8) * 40 + c0 + 8];
            }
            const int n0 = wn * 32 + (lane >> 2);
#pragma unroll
            for (int nj = 0; nj < 4; nj++) {
                int nn = n0 + nj * 8;
                b[nj][0] = *(const uint32_t*)&Bs[buf][nn * 40 + c0];
                b[nj][1] = *(const uint32_t*)&Bs[buf][nn * 40 + c0 + 8];
            }
#pragma unroll
            for (int mi = 0; mi < 2; mi++)
#pragma unroll
                for (int nj = 0; nj < 4; nj++)
                    asm volatile(
                        "mma.sync.aligned.m16n8k16.row.col.f32.bf16.bf16.f32 "
                        "{%0,%1,%2,%3},{%4,%5,%6,%7},{%8,%9},{%0,%1,%2,%3};\n"
                        : "+f"(acc[mi][nj][0]), "+f"(acc[mi][nj][1]),
                          "+f"(acc[mi][nj][2]), "+f"(acc[mi][nj][3])
                        : "r"(a[mi][0]), "r"(a[mi][1]), "r"(a[mi][2]), "r"(a[mi][3]),
                          "r"(b[nj][0]), "r"(b[nj][1]));
        }

        if (kt + 1 < KT) {
            CP_WAIT0();
            __syncthreads();
            buf ^= 1;
        }
    }

    // -------- epilogue --------
    const int r0  = wm * 32 + (lane >> 2);
    const int c0g = wn * 32 + (lane & 3) * 2;
#pragma unroll
    for (int mi = 0; mi < 2; mi++) {
#pragma unroll
        for (int p = 0; p < 2; p++) {
            const long gm = mbase + r0 + mi * 16 + p * 8;
            long drow = 0;
            if (MODE == 1) {
                int t = (int)gm;
                int wi = t / NTOK, n = t - wi * NTOK;
                int bimg = wi >> 6, win = wi & 63;
                int hh = (win >> 3) * WS + n / WS;
                int ww = (win & 7) * WS + n % WS;
                int h = hh + shift; if (h >= HH_) h -= HH_;
                int w = ww + shift; if (w >= WW_) w -= WW_;
                drow = ((long)bimg * (HH_ * WW_) + h * WW_ + w) * CC;
            }
#pragma unroll
            for (int nj = 0; nj < 4; nj++) {
#pragma unroll
                for (int q = 0; q < 2; q++) {
                    int gn = nbase + c0g + nj * 8 + q;
                    float v = acc[mi][nj][p * 2 + q] + bias[gn];
                    if (MODE == 0) {
                        if (gn < 192) v *= SCALE_Q;
                        outb[gm * 576 + gn] = __float2bfloat16(v);
                    } else if (MODE == 1) {
                        outf[drow + gn] += v;
                    } else if (MODE == 2) {
                        float g = 0.5f * v * (1.f + erff(v * 0.70710678118654752f));
                        outb[gm * 768 + gn] = __float2bfloat16(g);
                    } else {
                        outf[gm * CC + gn] += v;
                    }
                }
            }
        }
    }
}

// ----------------------------------------------------------------------------
// Windowed attention: one block per (window, head). 49x49 scores in smem,
// relative-position bias + shift mask computed analytically, fp32 softmax.
// ----------------------------------------------------------------------------
__global__ void __launch_bounds__(128) attn_kernel(
    const __nv_bfloat16* __restrict__ qkv,   // [MTOK, 576] (q pre-scaled)
    const float* __restrict__ rpb,           // [169, 6] for this layer
    __nv_bfloat16* __restrict__ out,         // [MTOK, 192]
    int shift)
{
    __shared__ float Qs[NTOK * 33], Ks[NTOK * 33], Vs[NTOK * 33], Ss[NTOK * 50];
    const int wi = blockIdx.x / HEADS;
    const int h  = blockIdx.x - wi * HEADS;
    const int tid = threadIdx.x;

    const __nv_bfloat16* base = qkv + (long)wi * NTOK * 576 + h * HDIM;
    for (int e = tid; e < NTOK * HDIM; e += 128) {
        int n = e >> 5, d = e & 31;
        const __nv_bfloat16* p = base + n * 576 + d;
        Qs[n * 33 + d] = __bfloat162float(p[0]);
        Ks[n * 33 + d] = __bfloat162float(p[192]);
        Vs[n * 33 + d] = __bfloat162float(p[384]);
    }
    __syncthreads();

    const int win = wi & 63;
    const int wrh = (win >> 3) * WS, wcw = (win & 7) * WS;

    for (int e = tid; e < NTOK * NTOK; e += 128) {
        int n = e / NTOK, m = e - n * NTOK;
        float s = 0.f;
#pragma unroll
        for (int d = 0; d < HDIM; d++) s += Qs[n * 33 + d] * Ks[m * 33 + d];
        int i1 = n / WS, j1 = n - i1 * WS;
        int i2 = m / WS, j2 = m - i2 * WS;
        int idx = (i1 - i2 + WS - 1) * (2 * WS - 1) + (j1 - j2 + WS - 1);
        s += __ldg(&rpb[idx * HEADS + h]);
        if (shift) {
            int r1 = region_of(wrh + i1) * 3 + region_of(wcw + j1);
            int r2 = region_of(wrh + i2) * 3 + region_of(wcw + j2);
            if (r1 != r2) s -= 100.f;
        }
        Ss[n * 50 + m] = s;
    }
    __syncthreads();

    // softmax: one warp per row
    const int warp = tid >> 5, lane = tid & 31;
    for (int r = warp; r < NTOK; r += 4) {
        float x0 = (lane < NTOK)      ? Ss[r * 50 + lane]      : -1e30f;
        float x1 = (lane + 32 < NTOK) ? Ss[r * 50 + lane + 32] : -1e30f;
        float mx = fmaxf(x0, x1);
#pragma unroll
        for (int o = 16; o > 0; o >>= 1) mx = fmaxf(mx, __shfl_xor_sync(0xffffffffu, mx, o));
        float e0 = (lane < NTOK)      ? expf(x0 - mx) : 0.f;
        float e1 = (lane + 32 < NTOK) ? expf(x1 - mx) : 0.f;
        float sm = e0 + e1;
#pragma unroll
        for (int o = 16; o > 0; o >>= 1) sm += __shfl_xor_sync(0xffffffffu, sm, o);
        float inv = 1.f / sm;
        if (lane < NTOK)      Ss[r * 50 + lane]      = e0 * inv;
        if (lane + 32 < NTOK) Ss[r * 50 + lane + 32] = e1 * inv;
    }
    __syncthreads();

    __nv_bfloat16* op = out + (long)wi * NTOK * CC + h * HDIM;
    for (int e = tid; e < NTOK * HDIM; e += 128) {
        int n = e >> 5, d = e & 31;
        float s = 0.f;
#pragma unroll
        for (int m = 0; m < NTOK; m++) s += Ss[n * 50 + m] * Vs[m * 33 + d];
        op[n * CC + d] = __float2bfloat16(s);
    }
}

// ----------------------------------------------------------------------------
// Launch
// ----------------------------------------------------------------------------
extern "C" void kernel_launch(void* const* d_in, const int* in_sizes, int n_in,
                              void* d_out, int out_size) {
    const float* x      = (const float*)d_in[0];
    const float* ln1_g  = (const float*)d_in[1];
    const float* ln1_b  = (const float*)d_in[2];
    const float* qkv_w  = (const float*)d_in[3];
    const float* qkv_b  = (const float*)d_in[4];
    const float* rpb    = (const float*)d_in[5];
    const float* proj_w = (const float*)d_in[6];
    const float* proj_b = (const float*)d_in[7];
    const float* ln2_g  = (const float*)d_in[8];
    const float* ln2_b  = (const float*)d_in[9];
    const float* fc1_w  = (const float*)d_in[10];
    const float* fc1_b  = (const float*)d_in[11];
    const float* fc2_w  = (const float*)d_in[12];
    const float* fc2_b  = (const float*)d_in[13];
    float* xbuf = (float*)d_out;

    __nv_bfloat16 *xw, *qkvb, *attnb, *h1, *wq, *wp, *w1, *w2;
    cudaGetSymbolAddress((void**)&xw,    g_xw);
    cudaGetSymbolAddress((void**)&qkvb,  g_qkv);
    cudaGetSymbolAddress((void**)&attnb, g_attn);
    cudaGetSymbolAddress((void**)&h1,    g_h1);
    cudaGetSymbolAddress((void**)&wq,    g_wqkv);
    cudaGetSymbolAddress((void**)&wp,    g_wproj);
    cudaGetSymbolAddress((void**)&w1,    g_wfc1);
    cudaGetSymbolAddress((void**)&w2,    g_wfc2);

    // residual stream = d_out
    copy_kernel<<<(MTOK * CC / 4 + 255) / 256, 256>>>((const float4*)x, (float4*)xbuf, MTOK * CC / 4);

    // weight transposes (both depths)
    for (int d = 0; d < 2; d++) {
        transpose_kernel<<<(192 * 576 + 255) / 256, 256>>>(qkv_w  + d * 192 * 576, wq + d * 576 * 192, 192, 576);
        transpose_kernel<<<(192 * 192 + 255) / 256, 256>>>(proj_w + d * 192 * 192, wp + d * 192 * 192, 192, 192);
        transpose_kernel<<<(192 * 768 + 255) / 256, 256>>>(fc1_w  + d * 192 * 768, w1 + d * 768 * 192, 192, 768);
        transpose_kernel<<<(768 * 192 + 255) / 256, 256>>>(fc2_w  + d * 768 * 192, w2 + d * 192 * 768, 768, 192);
    }

    const int MT = MTOK / 128;   // 1568
    for (int d = 0; d < 2; d++) {
        int shift = (d & 1) ? 3 : 0;

        // LN1 + shift + window partition -> bf16
        ln_kernel<<<MTOK / 8, 256>>>(xbuf, ln1_g + d * CC, ln1_b + d * CC, xw, shift, 1);

        // qkv GEMM [M,192]x[192,576]
        gemm_k<0><<<dim3(9, MT), 256>>>(xw, wq + d * 576 * 192, qkv_b + d * 576, qkvb, nullptr, 192, 0);

        // attention per (window, head)
        attn_kernel<<<NWIN_TOT * HEADS, 128>>>(qkvb, rpb + d * 169 * HEADS, attnb, shift);

        // proj GEMM + window reverse + roll + residual add
        gemm_k<1><<<dim3(3, MT), 256>>>(attnb, wp + d * 192 * 192, proj_b + d * CC, nullptr, xbuf, 192, shift);

        // LN2 -> bf16 (linear order; reuse xw)
        ln_kernel<<<MTOK / 8, 256>>>(xbuf, ln2_g + d * CC, ln2_b + d * CC, xw, 0, 0);

        // fc1 GEMM + GELU
        gemm_k<2><<<dim3(12, MT), 256>>>(xw, w1 + d * 768 * 192, fc1_b + d * HID, h1, nullptr, 192, 0);

        // fc2 GEMM + residual add
        gemm_k<3><<<dim3(3, MT), 256>>>(h1, w2 + d * 192 * 768, fc2_b + d * CC, nullptr, xbuf, 768, 0);
    }
}

// round 12
// speedup vs baseline: 1.0184x; 1.0184x over previous
#include <cuda_runtime.h>
#include <cuda_bf16.h>
#include <cstdint>
#include <math.h>

// ----------------------------------------------------------------------------
// Problem constants
// ----------------------------------------------------------------------------
#define BQ    64
#define HH_   56
#define WW_   56
#define CC    192
#define HEADS 6
#define WS    7
#define NWIN_TOT 4096          // B * 64 windows
#define NTOK  49               // WS*WS
#define HDIM  32
#define HID   768
#define MTOK  200704           // B*H*W = NWIN_TOT*NTOK
#define SCALE_Q 0.17677669529663687f

// ----------------------------------------------------------------------------
// Scratch (device globals — allocation-free per harness rules)
// ----------------------------------------------------------------------------
__device__ __nv_bfloat16 g_xw  [(size_t)MTOK * 192];   // LN output (windowed or linear)
__device__ __nv_bfloat16 g_qkv [(size_t)MTOK * 576];
__device__ __nv_bfloat16 g_attn[(size_t)MTOK * 192];
__device__ __nv_bfloat16 g_h1  [(size_t)MTOK * 768];
__device__ __nv_bfloat16 g_wqkv[2 * 576 * 192];        // transposed [N,K] bf16
__device__ __nv_bfloat16 g_wproj[2 * 192 * 192];
__device__ __nv_bfloat16 g_wfc1[2 * 768 * 192];
__device__ __nv_bfloat16 g_wfc2[2 * 192 * 768];

// ----------------------------------------------------------------------------
// Helpers
// ----------------------------------------------------------------------------
__device__ __forceinline__ void cp_async16(void* smem_ptr, const void* gmem_ptr) {
    uint32_t s = (uint32_t)__cvta_generic_to_shared(smem_ptr);
    asm volatile("cp.async.cg.shared.global [%0], [%1], 16;\n" :: "r"(s), "l"(gmem_ptr));
}
#define CP_COMMIT() asm volatile("cp.async.commit_group;\n")
#define CP_WAIT0()  asm volatile("cp.async.wait_group 0;\n")

__device__ __forceinline__ int region_of(int h) {
    return (h < HH_ - WS) ? 0 : ((h < HH_ - 3) ? 1 : 2);  // shift = 3
}

// ----------------------------------------------------------------------------
// Copy x -> d_out (residual stream lives in d_out, f32)
// ----------------------------------------------------------------------------
__global__ void copy_kernel(const float4* __restrict__ src, float4* __restrict__ dst, int n) {
    int i = blockIdx.x * blockDim.x + threadIdx.x;
    if (i < n) dst[i] = src[i];
}

// ----------------------------------------------------------------------------
// Weight transpose + cast: w[K,N] f32 -> wt[N,K] bf16
// ----------------------------------------------------------------------------
__global__ void transpose_kernel(const float* __restrict__ w, __nv_bfloat16* __restrict__ wt,
                                 int K, int N) {
    int i = blockIdx.x * blockDim.x + threadIdx.x;
    if (i < K * N) {
        int k = i / N, n = i - k * N;
        wt[n * K + k] = __float2bfloat16(w[i]);
    }
}

// ----------------------------------------------------------------------------
// LayerNorm (+optional shift + window partition) -> bf16
// windowed=1: out token t = window token (with roll by -shift); windowed=0: identity order
// one warp per token, 8 tokens per 256-thread block
// ----------------------------------------------------------------------------
__global__ void __launch_bounds__(256) ln_kernel(
    const float* __restrict__ x,
    const float* __restrict__ gamma,
    const float* __restrict__ beta,
    __nv_bfloat16* __restrict__ out,
    int shift, int windowed)
{
    int warp = threadIdx.x >> 5, lane = threadIdx.x & 31;
    int t = blockIdx.x * 8 + warp;   // < MTOK
    long src;
    if (windowed) {
        int wi = t / NTOK, n = t - wi * NTOK;
        int bimg = wi >> 6, win = wi & 63;
        int hh = (win >> 3) * WS + n / WS;
        int ww = (win & 7) * WS + n % WS;
        int h = hh + shift; if (h >= HH_) h -= HH_;
        int w = ww + shift; if (w >= WW_) w -= WW_;
        src = (long)bimg * (HH_ * WW_) + h * WW_ + w;
    } else {
        src = t;
    }
    const float* xp = x + src * CC;
    float v[6], s = 0.f, s2 = 0.f;
#pragma unroll
    for (int j = 0; j < 6; j++) {
        v[j] = xp[lane + 32 * j];
        s += v[j]; s2 += v[j] * v[j];
    }
#pragma unroll
    for (int o = 16; o > 0; o >>= 1) {
        s  += __shfl_xor_sync(0xffffffffu, s,  o);
        s2 += __shfl_xor_sync(0xffffffffu, s2, o);
    }
    float mu  = s * (1.f / CC);
    float var = s2 * (1.f / CC) - mu * mu;
    float rstd = rsqrtf(var + 1e-5f);
    __nv_bfloat16* op = out + (long)t * CC;
#pragma unroll
    for (int j = 0; j < 6; j++) {
        int c = lane + 32 * j;
        op[c] = __float2bfloat16((v[j] - mu) * rstd * gamma[c] + beta[c]);
    }
}

// ----------------------------------------------------------------------------
// GEMM: C[M, N] = A[M, K] (bf16) @ Bt[N, K]^T (bf16), fp32 accum, fused epilogues
// Tiles: BM=128, BN=64, BK=32; 256 threads, 8 warps (4x2), warp tile 32x32,
// mma.sync.m16n8k16. M is 200704 (grid.y), K in {192,768}, N in {576,192,768,192}.
// MODE 0: qkv  (bias, q-cols *= SCALE, -> bf16 [M,576])
// MODE 1: proj (bias, window-reverse + roll + residual add into f32 x)
// MODE 2: fc1  (bias + exact GELU -> bf16 [M,768])
// MODE 3: fc2  (bias + residual add into f32 x [M,192])
// ----------------------------------------------------------------------------
template<int MODE>
__global__ void __launch_bounds__(256, 1) gemm_k(
    const __nv_bfloat16* __restrict__ A,
    const __nv_bfloat16* __restrict__ Bt,
    const float* __restrict__ bias,
    __nv_bfloat16* __restrict__ outb,
    float* __restrict__ outf,
    int K, int shift)
{
    __shared__ __nv_bfloat16 As[2][128 * 40];
    __shared__ __nv_bfloat16 Bs[2][64 * 40];

    const int tid  = threadIdx.x;
    const int lane = tid & 31, warp = tid >> 5;
    const int wm = warp >> 1, wn = warp & 1;
    const long mbase = (long)blockIdx.y * 128;
    const int  nbase = blockIdx.x * 64;

    const __nv_bfloat16* Ag = A  + mbase * K;
    const __nv_bfloat16* Bg = Bt + (long)nbase * K;

    const int lrow = tid >> 2;        // 0..63
    const int lcol = (tid & 3) * 8;   // 0,8,16,24

    float acc[2][4][4];
#pragma unroll
    for (int i = 0; i < 2; i++)
#pragma unroll
        for (int j = 0; j < 4; j++)
#pragma unroll
            for (int e = 0; e < 4; e++) acc[i][j][e] = 0.f;

    const int KT = K / 32;

    auto loadst = [&](int buf, int kt) {
        int kb = kt * 32;
        cp_async16(&As[buf][ lrow       * 40 + lcol], Ag + (long)lrow        * K + kb + lcol);
        cp_async16(&As[buf][(lrow + 64) * 40 + lcol], Ag + (long)(lrow + 64) * K + kb + lcol);
        cp_async16(&Bs[buf][ lrow       * 40 + lcol], Bg + (long)lrow        * K + kb + lcol);
        CP_COMMIT();
    };

    loadst(0, 0);
    CP_WAIT0();
    __syncthreads();

    int buf = 0;
    for (int kt = 0; kt < KT; kt++) {
        if (kt + 1 < KT) loadst(buf ^ 1, kt + 1);

#pragma unroll
        for (int kk = 0; kk < 2; kk++) {
            const int c0 = kk * 16 + (lane & 3) * 2;
            uint32_t a[2][4], b[4][2];
            const int r0 = wm * 32 + (lane >> 2);
#pragma unroll
            for (int mi = 0; mi < 2; mi++) {
                int rr = r0 + mi * 16;
                a[mi][0] = *(const uint32_t*)&As[buf][ rr      * 40 + c0];
                a[mi][1] = *(const uint32_t*)&As[buf][(rr + 8) * 40 + c0];
                a[mi][2] = *(const uint32_t*)&As[buf][ rr      * 40 + c0 + 8];
                a[mi][3] = *(const uint32_t*)&As[buf][(rr + 8) * 40 + c0 + 8];
            }
            const int n0 = wn * 32 + (lane >> 2);
#pragma unroll
            for (int nj = 0; nj < 4; nj++) {
                int nn = n0 + nj * 8;
                b[nj][0] = *(const uint32_t*)&Bs[buf][nn * 40 + c0];
                b[nj][1] = *(const uint32_t*)&Bs[buf][nn * 40 + c0 + 8];
            }
#pragma unroll
            for (int mi = 0; mi < 2; mi++)
#pragma unroll
                for (int nj = 0; nj < 4; nj++)
                    asm volatile(
                        "mma.sync.aligned.m16n8k16.row.col.f32.bf16.bf16.f32 "
                        "{%0,%1,%2,%3},{%4,%5,%6,%7},{%8,%9},{%0,%1,%2,%3};\n"
                        : "+f"(acc[mi][nj][0]), "+f"(acc[mi][nj][1]),
                          "+f"(acc[mi][nj][2]), "+f"(acc[mi][nj][3])
                        : "r"(a[mi][0]), "r"(a[mi][1]), "r"(a[mi][2]), "r"(a[mi][3]),
                          "r"(b[nj][0]), "r"(b[nj][1]));
        }

        if (kt + 1 < KT) {
            CP_WAIT0();
            __syncthreads();
            buf ^= 1;
        }
    }

    // -------- epilogue --------
    const int r0  = wm * 32 + (lane >> 2);
    const int c0g = wn * 32 + (lane & 3) * 2;
#pragma unroll
    for (int mi = 0; mi < 2; mi++) {
#pragma unroll
        for (int p = 0; p < 2; p++) {
            const long gm = mbase + r0 + mi * 16 + p * 8;
            long drow = 0;
            if (MODE == 1) {
                int t = (int)gm;
                int wi = t / NTOK, n = t - wi * NTOK;
                int bimg = wi >> 6, win = wi & 63;
                int hh = (win >> 3) * WS + n / WS;
                int ww = (win & 7) * WS + n % WS;
                int h = hh + shift; if (h >= HH_) h -= HH_;
                int w = ww + shift; if (w >= WW_) w -= WW_;
                drow = ((long)bimg * (HH_ * WW_) + h * WW_ + w) * CC;
            }
#pragma unroll
            for (int nj = 0; nj < 4; nj++) {
#pragma unroll
                for (int q = 0; q < 2; q++) {
                    int gn = nbase + c0g + nj * 8 + q;
                    float v = acc[mi][nj][p * 2 + q] + bias[gn];
                    if (MODE == 0) {
                        if (gn < 192) v *= SCALE_Q;
                        outb[gm * 576 + gn] = __float2bfloat16(v);
                    } else if (MODE == 1) {
                        outf[drow + gn] += v;
                    } else if (MODE == 2) {
                        float g = 0.5f * v * (1.f + erff(v * 0.70710678118654752f));
                        outb[gm * 768 + gn] = __float2bfloat16(g);
                    } else {
                        outf[gm * CC + gn] += v;
                    }
                }
            }
        }
    }
}

// ----------------------------------------------------------------------------
// Windowed attention: one block per (window, head). 49x49 scores in smem,
// relative-position bias + shift mask computed analytically, fp32 softmax.
// ----------------------------------------------------------------------------
__global__ void __launch_bounds__(128) attn_kernel(
    const __nv_bfloat16* __restrict__ qkv,   // [MTOK, 576] (q pre-scaled)
    const float* __restrict__ rpb,           // [169, 6] for this layer
    __nv_bfloat16* __restrict__ out,         // [MTOK, 192]
    int shift)
{
    __shared__ float Qs[NTOK * 33], Ks[NTOK * 33], Vs[NTOK * 33], Ss[NTOK * 50];
    const int wi = blockIdx.x / HEADS;
    const int h  = blockIdx.x - wi * HEADS;
    const int tid = threadIdx.x;

    const __nv_bfloat16* base = qkv + (long)wi * NTOK * 576 + h * HDIM;
    for (int e = tid; e < NTOK * HDIM; e += 128) {
        int n = e >> 5, d = e & 31;
        const __nv_bfloat16* p = base + n * 576 + d;
        Qs[n * 33 + d] = __bfloat162float(p[0]);
        Ks[n * 33 + d] = __bfloat162float(p[192]);
        Vs[n * 33 + d] = __bfloat162float(p[384]);
    }
    __syncthreads();

    const int win = wi & 63;
    const int wrh = (win >> 3) * WS, wcw = (win & 7) * WS;

    for (int e = tid; e < NTOK * NTOK; e += 128) {
        int n = e / NTOK, m = e - n * NTOK;
        float s = 0.f;
#pragma unroll
        for (int d = 0; d < HDIM; d++) s += Qs[n * 33 + d] * Ks[m * 33 + d];
        int i1 = n / WS, j1 = n - i1 * WS;
        int i2 = m / WS, j2 = m - i2 * WS;
        int idx = (i1 - i2 + WS - 1) * (2 * WS - 1) + (j1 - j2 + WS - 1);
        s += __ldg(&rpb[idx * HEADS + h]);
        if (shift) {
            int r1 = region_of(wrh + i1) * 3 + region_of(wcw + j1);
            int r2 = region_of(wrh + i2) * 3 + region_of(wcw + j2);
            if (r1 != r2) s -= 100.f;
        }
        Ss[n * 50 + m] = s;
    }
    __syncthreads();

    // softmax: one warp per row
    const int warp = tid >> 5, lane = tid & 31;
    for (int r = warp; r < NTOK; r += 4) {
        float x0 = (lane < NTOK)      ? Ss[r * 50 + lane]      : -1e30f;
        float x1 = (lane + 32 < NTOK) ? Ss[r * 50 + lane + 32] : -1e30f;
        float mx = fmaxf(x0, x1);
#pragma unroll
        for (int o = 16; o > 0; o >>= 1) mx = fmaxf(mx, __shfl_xor_sync(0xffffffffu, mx, o));
        float e0 = (lane < NTOK)      ? expf(x0 - mx) : 0.f;
        float e1 = (lane + 32 < NTOK) ? expf(x1 - mx) : 0.f;
        float sm = e0 + e1;
#pragma unroll
        for (int o = 16; o > 0; o >>= 1) sm += __shfl_xor_sync(0xffffffffu, sm, o);
        float inv = 1.f / sm;
        if (lane < NTOK)      Ss[r * 50 + lane]      = e0 * inv;
        if (lane + 32 < NTOK) Ss[r * 50 + lane + 32] = e1 * inv;
    }
    __syncthreads();

    __nv_bfloat16* op = out + (long)wi * NTOK * CC + h * HDIM;
    for (int e = tid; e < NTOK * HDIM; e += 128) {
        int n = e >> 5, d = e & 31;
        float s = 0.f;
#pragma unroll
        for (int m = 0; m < NTOK; m++) s += Ss[n * 50 + m] * Vs[m * 33 + d];
        op[n * CC + d] = __float2bfloat16(s);
    }
}

// ----------------------------------------------------------------------------
// Launch
// ----------------------------------------------------------------------------
extern "C" void kernel_launch(void* const* d_in, const int* in_sizes, int n_in,
                              void* d_out, int out_size) {
    const float* x      = (const float*)d_in[0];
    const float* ln1_g  = (const float*)d_in[1];
    const float* ln1_b  = (const float*)d_in[2];
    const float* qkv_w  = (const float*)d_in[3];
    const float* qkv_b  = (const float*)d_in[4];
    const float* rpb    = (const float*)d_in[5];
    const float* proj_w = (const float*)d_in[6];
    const float* proj_b = (const float*)d_in[7];
    const float* ln2_g  = (const float*)d_in[8];
    const float* ln2_b  = (const float*)d_in[9];
    const float* fc1_w  = (const float*)d_in[10];
    const float* fc1_b  = (const float*)d_in[11];
    const float* fc2_w  = (const float*)d_in[12];
    const float* fc2_b  = (const float*)d_in[13];
    float* xbuf = (float*)d_out;

    __nv_bfloat16 *xw, *qkvb, *attnb, *h1, *wq, *wp, *w1, *w2;
    cudaGetSymbolAddress((void**)&xw,    g_xw);
    cudaGetSymbolAddress((void**)&qkvb,  g_qkv);
    cudaGetSymbolAddress((void**)&attnb, g_attn);
    cudaGetSymbolAddress((void**)&h1,    g_h1);
    cudaGetSymbolAddress((void**)&wq,    g_wqkv);
    cudaGetSymbolAddress((void**)&wp,    g_wproj);
    cudaGetSymbolAddress((void**)&w1,    g_wfc1);
    cudaGetSymbolAddress((void**)&w2,    g_wfc2);

    // residual stream = d_out
    copy_kernel<<<(MTOK * CC / 4 + 255) / 256, 256>>>((const float4*)x, (float4*)xbuf, MTOK * CC / 4);

    // weight transposes (both depths)
    for (int d = 0; d < 2; d++) {
        transpose_kernel<<<(192 * 576 + 255) / 256, 256>>>(qkv_w  + d * 192 * 576, wq + d * 576 * 192, 192, 576);
        transpose_kernel<<<(192 * 192 + 255) / 256, 256>>>(proj_w + d * 192 * 192, wp + d * 192 * 192, 192, 192);
        transpose_kernel<<<(192 * 768 + 255) / 256, 256>>>(fc1_w  + d * 192 * 768, w1 + d * 768 * 192, 192, 768);
        transpose_kernel<<<(768 * 192 + 255) / 256, 256>>>(fc2_w  + d * 768 * 192, w2 + d * 192 * 768, 768, 192);
    }

    const int MT = MTOK / 128;   // 1568
    for (int d = 0; d < 2; d++) {
        int shift = (d & 1) ? 3 : 0;

        // LN1 + shift + window partition -> bf16
        ln_kernel<<<MTOK / 8, 256>>>(xbuf, ln1_g + d * CC, ln1_b + d * CC, xw, shift, 1);

        // qkv GEMM [M,192]x[192,576]
        gemm_k<0><<<dim3(9, MT), 256>>>(xw, wq + d * 576 * 192, qkv_b + d * 576, qkvb, nullptr, 192, 0);

        // attention per (window, head)
        attn_kernel<<<NWIN_TOT * HEADS, 128>>>(qkvb, rpb + d * 169 * HEADS, attnb, shift);

        // proj GEMM + window reverse + roll + residual add
        gemm_k<1><<<dim3(3, MT), 256>>>(attnb, wp + d * 192 * 192, proj_b + d * CC, nullptr, xbuf, 192, shift);

        // LN2 -> bf16 (linear order; reuse xw)
        ln_kernel<<<MTOK / 8, 256>>>(xbuf, ln2_g + d * CC, ln2_b + d * CC, xw, 0, 0);

        // fc1 GEMM + GELU
        gemm_k<2><<<dim3(12, MT), 256>>>(xw, w1 + d * 768 * 192, fc1_b + d * HID, h1, nullptr, 192, 0);

        // fc2 GEMM + residual add
        gemm_k<3><<<dim3(3, MT), 256>>>(h1, w2 + d * 192 * 768, fc2_b + d * CC, nullptr, xbuf, 768, 0);
    }
}